// round 17
// baseline (speedup 1.0000x reference)
#include <cuda_runtime.h>
#include <cuda_bf16.h>
#include <math.h>

#define NMAX  100000
#define EMAX  1600000
#define F_IN  256
#define HID   64
#define NCLS  40

// ---------------- device scratch ----------------
__device__ float    g_dis[NMAX];
__device__ int      g_cnt[NMAX];
__device__ int      g_ptr[NMAX];
__device__ int      g_rank[EMAX];
__device__ int      g_total;
__device__ int      g_edge[EMAX];             // src only, grouped by dst
__device__ unsigned g_h1 [NMAX * (HID / 2)];  // x @ W1, bf16x2 packed
__device__ unsigned g_a1 [NMAX * (HID / 2)];  // relu(agg1 + b1), bf16x2 packed
__device__ unsigned g_h2 [NMAX * (NCLS / 2)]; // a1 @ W2, bf16x2 packed

// ---------------- CSR build ----------------
__global__ void k_zero(int* cnt, int* total, int n) {
    int i = blockIdx.x * blockDim.x + threadIdx.x;
    if (i < n) cnt[i] = 0;
    if (i == 0) *total = 0;
}

// histogram + per-edge rank, 8 edges/thread
__global__ void k_hist(const int* __restrict__ col, int* cnt, int* rank, int E) {
    int i = blockIdx.x * blockDim.x + threadIdx.x;
    int e0 = 8 * i;
    if (e0 + 8 <= E) {
        int4 c0 = *reinterpret_cast<const int4*>(col + e0);
        int4 c1 = *reinterpret_cast<const int4*>(col + e0 + 4);
        int r0 = atomicAdd(&cnt[c0.x], 1);
        int r1 = atomicAdd(&cnt[c0.y], 1);
        int r2 = atomicAdd(&cnt[c0.z], 1);
        int r3 = atomicAdd(&cnt[c0.w], 1);
        int r4 = atomicAdd(&cnt[c1.x], 1);
        int r5 = atomicAdd(&cnt[c1.y], 1);
        int r6 = atomicAdd(&cnt[c1.z], 1);
        int r7 = atomicAdd(&cnt[c1.w], 1);
        *reinterpret_cast<int4*>(rank + e0)     = make_int4(r0, r1, r2, r3);
        *reinterpret_cast<int4*>(rank + e0 + 4) = make_int4(r4, r5, r6, r7);
    } else {
        for (int e = e0; e < E; e++) rank[e] = atomicAdd(&cnt[col[e]], 1);
    }
}

__global__ void k_ptr(const int* __restrict__ cnt, int* ptr,
                      float* dis, int* total, int n) {
    __shared__ int wsum[8];
    __shared__ int wbase;
    int i = blockIdx.x * blockDim.x + threadIdx.x;
    int lane = threadIdx.x & 31, w = threadIdx.x >> 5;
    int v = (i < n) ? cnt[i] : 0;
    int s = v;
#pragma unroll
    for (int o = 1; o < 32; o <<= 1) {
        int t = __shfl_up_sync(0xffffffffu, s, o);
        if (lane >= o) s += t;
    }
    if (lane == 31) wsum[w] = s;
    __syncthreads();
    if (threadIdx.x == 0) {
        int t = 0;
#pragma unroll
        for (int k = 0; k < 8; k++) { int x = wsum[k]; wsum[k] = t; t += x; }
        wbase = atomicAdd(total, t);
    }
    __syncthreads();
    if (i < n) {
        ptr[i] = wbase + wsum[w] + s - v;
        dis[i] = rsqrtf((float)(v + 1));
    }
}

// non-atomic scatter, 8 edges/thread
__global__ void k_scat(const int* __restrict__ row, const int* __restrict__ col,
                       const int* __restrict__ ptr, const int* __restrict__ rank,
                       int* edge, int E) {
    int i = blockIdx.x * blockDim.x + threadIdx.x;
    int e0 = 8 * i;
    if (e0 + 8 <= E) {
        int4 r0 = *reinterpret_cast<const int4*>(row + e0);
        int4 r1 = *reinterpret_cast<const int4*>(row + e0 + 4);
        int4 c0 = *reinterpret_cast<const int4*>(col + e0);
        int4 c1 = *reinterpret_cast<const int4*>(col + e0 + 4);
        int4 k0 = *reinterpret_cast<const int4*>(rank + e0);
        int4 k1 = *reinterpret_cast<const int4*>(rank + e0 + 4);
        int p0 = ptr[c0.x], p1 = ptr[c0.y], p2 = ptr[c0.z], p3 = ptr[c0.w];
        int p4 = ptr[c1.x], p5 = ptr[c1.y], p6 = ptr[c1.z], p7 = ptr[c1.w];
        edge[p0 + k0.x] = r0.x;
        edge[p1 + k0.y] = r0.y;
        edge[p2 + k0.z] = r0.z;
        edge[p3 + k0.w] = r0.w;
        edge[p4 + k1.x] = r1.x;
        edge[p5 + k1.y] = r1.y;
        edge[p6 + k1.z] = r1.z;
        edge[p7 + k1.w] = r1.w;
    } else {
        for (int e = e0; e < E; e++) edge[ptr[col[e]] + rank[e]] = row[e];
    }
}

// ---------------- helpers ----------------
__device__ __forceinline__ void mma_bf16(float* d, const unsigned* a,
                                         unsigned b0, unsigned b1) {
    asm volatile(
        "mma.sync.aligned.m16n8k16.row.col.f32.bf16.bf16.f32 "
        "{%0,%1,%2,%3}, {%4,%5,%6,%7}, {%8,%9}, {%0,%1,%2,%3};"
        : "+f"(d[0]), "+f"(d[1]), "+f"(d[2]), "+f"(d[3])
        : "r"(a[0]), "r"(a[1]), "r"(a[2]), "r"(a[3]), "r"(b0), "r"(b1));
}

__device__ __forceinline__ unsigned packbf(float v0, float v1) {
    unsigned r;
    asm("cvt.rn.bf16x2.f32 %0, %1, %2;" : "=r"(r) : "f"(v1), "f"(v0));
    return r;
}

__device__ __forceinline__ float2 bf2f(unsigned u) {
    return make_float2(__int_as_float(u << 16), __int_as_float(u & 0xffff0000u));
}

// ---------------- GEMM1: h1 = x @ W1, bf16 mma (x,W both bf16), A from global
// smem: B hi words [0..8191]   (32 KB)
#define SMEM1_BYTES (8192 * 4)

__global__ void __launch_bounds__(256, 2) k_gemm1(
    const float* __restrict__ x, const float* __restrict__ W,
    unsigned* __restrict__ h, int n)
{
    extern __shared__ uint4 sm4[];
    unsigned* smw = reinterpret_cast<unsigned*>(sm4);

    const int tid  = threadIdx.x;
    const int lane = tid & 31, wid = tid >> 5;
    const int base = blockIdx.x * 256;

    // ---- stage W1 (64 n x 256 k) into B fragment layout (bf16) ----
    for (int idx = tid; idx < 64 * 128; idx += 256) {
        int nn = idx & 63, k2 = idx >> 6;
        int k = 2 * k2;
        unsigned hi = packbf(W[k * HID + nn], W[(k + 1) * HID + nn]);
        int s = k2 >> 3, k2l = k2 & 7;
        int j = nn >> 3, r = nn & 7, jp = j >> 1, jl = j & 1;
        int c = k2l & 3, hh = k2l >> 2;
        int widx = (((s * 4 + jp) * 32) + (4 * r + c)) * 4 + (jl * 2 + hh);
        smw[widx] = hi;
    }
    __syncthreads();                          // one-time; loop is sync-free

    float acc[2][8][4];
#pragma unroll
    for (int m = 0; m < 2; m++)
#pragma unroll
        for (int j = 0; j < 8; j++)
#pragma unroll
            for (int q = 0; q < 4; q++) acc[m][j][q] = 0.f;

    // A-fragment source rows/cols for this lane (direct global load)
    const int g  = lane >> 2;                 // row-in-tile 0..7
    const int q  = lane & 3;                  // col pair selector
    const float2* fp2[8];
#pragma unroll
    for (int m = 0; m < 2; m++) {
        int r1 = base + wid * 32 + m * 16 + g;
        int r2 = r1 + 8;
        int r1c = r1 < n ? r1 : n - 1;
        int r2c = r2 < n ? r2 : n - 1;
        const float2* p1 = reinterpret_cast<const float2*>(x + (size_t)r1c * F_IN) + q;
        const float2* p2 = reinterpret_cast<const float2*>(x + (size_t)r2c * F_IN) + q;
        fp2[m * 4 + 0] = p1;          // a0: (r1, klow)
        fp2[m * 4 + 1] = p2;          // a1: (r2, klow)
        fp2[m * 4 + 2] = p1 + 4;      // a2: (r1, khigh)
        fp2[m * 4 + 3] = p2 + 4;      // a3: (r2, khigh)
    }

    // 2-deep prefetch pipeline
    float2 cur[8], nxt[8];
#pragma unroll
    for (int i = 0; i < 8; i++) cur[i] = fp2[i][0];
#pragma unroll
    for (int i = 0; i < 8; i++) nxt[i] = fp2[i][8];

    const uint4* Bq = sm4;

    for (int s = 0; s < F_IN / 16; s++) {
        // convert current k-step to bf16 fragments (1 cvt per reg)
        unsigned ahi[2][4];
#pragma unroll
        for (int m = 0; m < 2; m++)
#pragma unroll
            for (int j = 0; j < 4; j++)
                ahi[m][j] = packbf(cur[m * 4 + j].x, cur[m * 4 + j].y);

        // rotate pipeline: cur <- nxt, issue loads for s+2
#pragma unroll
        for (int i = 0; i < 8; i++) cur[i] = nxt[i];
        if (s + 2 < F_IN / 16) {
#pragma unroll
            for (int i = 0; i < 8; i++) nxt[i] = fp2[i][8 * (s + 2)];
        }

#pragma unroll
        for (int jp = 0; jp < 4; jp++) {
            uint4 bh = Bq[(s * 4 + jp) * 32 + lane];
#pragma unroll
            for (int m = 0; m < 2; m++) {
                mma_bf16(acc[m][2 * jp],     ahi[m], bh.x, bh.y);
                mma_bf16(acc[m][2 * jp + 1], ahi[m], bh.z, bh.w);
            }
        }
    }

    const int rr = lane >> 2, qq = lane & 3;
#pragma unroll
    for (int m = 0; m < 2; m++) {
        int r0 = base + wid * 32 + m * 16 + rr;
#pragma unroll
        for (int j = 0; j < 8; j++) {
            int cw = j * 4 + qq;                    // word index (= col/2)
            if (r0 < n)
                h[(size_t)r0 * (HID / 2) + cw] = packbf(acc[m][j][0], acc[m][j][1]);
            if (r0 + 8 < n)
                h[(size_t)(r0 + 8) * (HID / 2) + cw] = packbf(acc[m][j][2], acc[m][j][3]);
        }
    }
}

// ---------------- agg layer 1 + bias + relu, half-warp/node, bf16 in/out
__global__ void __launch_bounds__(256) k_agg1(
    const unsigned* __restrict__ h, const int* __restrict__ edge,
    const int* __restrict__ ptr, const int* __restrict__ cnt,
    const float* __restrict__ dis, const float* __restrict__ b,
    unsigned* __restrict__ out, int n)
{
    int g = (blockIdx.x * blockDim.x + threadIdx.x) >> 4;
    int c = threadIdx.x & 15;
    if (g >= n) return;
    const uint2* h8 = reinterpret_cast<const uint2*>(h);   // 16 uint2 per row
    float dg = dis[g];

    uint2 us = h8[(size_t)g * 16 + c];
    float2 sa = bf2f(us.x), sb = bf2f(us.y);
    float4 acc = make_float4(sa.x * dg, sa.y * dg, sb.x * dg, sb.y * dg);

    int e = ptr[g], end = e + cnt[g];
    for (; e + 8 <= end; e += 8) {
        int   p[8];
        float nn[8];
        uint2 v[8];
#pragma unroll
        for (int t = 0; t < 8; t++) p[t] = edge[e + t];
#pragma unroll
        for (int t = 0; t < 8; t++) v[t] = h8[(size_t)p[t] * 16 + c];
#pragma unroll
        for (int t = 0; t < 8; t++) nn[t] = dis[p[t]];
#pragma unroll
        for (int t = 0; t < 8; t++) {
            float2 a = bf2f(v[t].x), d = bf2f(v[t].y);
            acc.x += a.x * nn[t];
            acc.y += a.y * nn[t];
            acc.z += d.x * nn[t];
            acc.w += d.y * nn[t];
        }
    }
    for (; e < end; e++) {
        int p = edge[e];
        float nn = dis[p];
        uint2 u = h8[(size_t)p * 16 + c];
        float2 a = bf2f(u.x), d = bf2f(u.y);
        acc.x += a.x * nn; acc.y += a.y * nn; acc.z += d.x * nn; acc.w += d.y * nn;
    }
    float4 bv = reinterpret_cast<const float4*>(b)[c];
    float o0 = fmaxf(acc.x * dg + bv.x, 0.f);
    float o1 = fmaxf(acc.y * dg + bv.y, 0.f);
    float o2 = fmaxf(acc.z * dg + bv.z, 0.f);
    float o3 = fmaxf(acc.w * dg + bv.w, 0.f);
    reinterpret_cast<uint2*>(out)[(size_t)g * 16 + c] =
        make_uint2(packbf(o0, o1), packbf(o2, o3));
}

// ---------------- GEMM2: h2 = a1(bf16) @ W2 (64 -> 40), fp32 tiled, bf16 out
__global__ void __launch_bounds__(128) k_gemm2(
    const unsigned* __restrict__ a, const float* __restrict__ W,
    unsigned* __restrict__ h, int n)
{
    __shared__ float As[16][256];
    __shared__ float Bs[64][48];
    const int tid = threadIdx.x;
    const int tn = tid & 3;
    const int tm = tid >> 2;
    const int base = blockIdx.x * 256;

    for (int i = tid; i < 64 * 48; i += 128) {
        int r = i / 48, qq = i % 48, g = qq / 12, c = qq % 12;
        Bs[r][qq] = (c < 10) ? W[r * NCLS + g * 10 + c] : 0.f;
    }

    float acc[8][10];
#pragma unroll
    for (int i = 0; i < 8; i++)
#pragma unroll
        for (int j = 0; j < 10; j++) acc[i][j] = 0.f;

    const uint4* a4 = reinterpret_cast<const uint4*>(a);   // 8 uint4 per row
    int r0 = base + tid, r1 = base + tid + 128;

    for (int s = 0; s < 4; s++) {
        uint4 u0 = make_uint4(0,0,0,0), u1 = make_uint4(0,0,0,0);
        uint4 w0 = make_uint4(0,0,0,0), w1 = make_uint4(0,0,0,0);
        if (r0 < n) { u0 = a4[(size_t)r0 * 8 + 2 * s]; u1 = a4[(size_t)r0 * 8 + 2 * s + 1]; }
        if (r1 < n) { w0 = a4[(size_t)r1 * 8 + 2 * s]; w1 = a4[(size_t)r1 * 8 + 2 * s + 1]; }
        float f0[16], f1[16];
        {
            unsigned uu0[8] = {u0.x,u0.y,u0.z,u0.w,u1.x,u1.y,u1.z,u1.w};
            unsigned ww0[8] = {w0.x,w0.y,w0.z,w0.w,w1.x,w1.y,w1.z,w1.w};
#pragma unroll
            for (int t = 0; t < 8; t++) {
                float2 p = bf2f(uu0[t]); f0[2*t] = p.x; f0[2*t+1] = p.y;
                float2 r = bf2f(ww0[t]); f1[2*t] = r.x; f1[2*t+1] = r.y;
            }
        }
        __syncthreads();
#pragma unroll
        for (int k = 0; k < 16; k++) {
            As[k][tid]       = f0[k];
            As[k][tid + 128] = f1[k];
        }
        __syncthreads();
#pragma unroll
        for (int k = 0; k < 16; k++) {
            int kg = s * 16 + k;
            float4 A0 = reinterpret_cast<float4*>(As[k])[tm];
            float4 A1 = reinterpret_cast<float4*>(As[k])[tm + 32];
            const float* br = Bs[kg] + 12 * tn;
            float4 B0 = *reinterpret_cast<const float4*>(br);
            float4 B1 = *reinterpret_cast<const float4*>(br + 4);
            float2 B2 = *reinterpret_cast<const float2*>(br + 8);
            float am[8]  = {A0.x, A0.y, A0.z, A0.w, A1.x, A1.y, A1.z, A1.w};
            float bn[10] = {B0.x, B0.y, B0.z, B0.w, B1.x, B1.y, B1.z, B1.w, B2.x, B2.y};
#pragma unroll
            for (int i = 0; i < 8; i++)
#pragma unroll
                for (int j = 0; j < 10; j++) acc[i][j] += am[i] * bn[j];
        }
    }
#pragma unroll
    for (int i = 0; i < 8; i++) {
        int r = base + ((i < 4) ? (4 * tm + i) : (128 + 4 * tm + i - 4));
        if (r < n) {
            unsigned* hr = h + (size_t)r * (NCLS / 2) + 5 * tn;
#pragma unroll
            for (int j = 0; j < 5; j++)
                hr[j] = packbf(acc[i][2 * j], acc[i][2 * j + 1]);
        }
    }
}

// ---------------- agg layer 2 + bias + log_softmax, half-warp/node, bf16 gathers
__global__ void __launch_bounds__(256) k_agg2(
    const unsigned* __restrict__ h, const int* __restrict__ edge,
    const int* __restrict__ ptr, const int* __restrict__ cnt,
    const float* __restrict__ dis, const float* __restrict__ b,
    float* __restrict__ out, int n)
{
    int g = (blockIdx.x * blockDim.x + threadIdx.x) >> 4;
    int c = threadIdx.x & 15;
    if (g >= n) return;
    const bool live = c < (NCLS / 4);
    const int cl = live ? c : 0;
    const uint2* h8 = reinterpret_cast<const uint2*>(h);   // 10 uint2 per row
    float dg = dis[g];

    float4 acc = make_float4(0.f, 0.f, 0.f, 0.f);
    if (live) {
        uint2 us = h8[(size_t)g * 10 + c];
        float2 sa = bf2f(us.x), sb = bf2f(us.y);
        acc = make_float4(sa.x * dg, sa.y * dg, sb.x * dg, sb.y * dg);
    }
    int e = ptr[g], end = e + cnt[g];
    for (; e + 8 <= end; e += 8) {
        int   p[8];
        float nn[8];
#pragma unroll
        for (int t = 0; t < 8; t++) p[t] = edge[e + t];
        if (live) {
            uint2 v[8];
#pragma unroll
            for (int t = 0; t < 8; t++) v[t] = h8[(size_t)p[t] * 10 + cl];
#pragma unroll
            for (int t = 0; t < 8; t++) nn[t] = dis[p[t]];
#pragma unroll
            for (int t = 0; t < 8; t++) {
                float2 a = bf2f(v[t].x), d = bf2f(v[t].y);
                acc.x += a.x * nn[t];
                acc.y += a.y * nn[t];
                acc.z += d.x * nn[t];
                acc.w += d.y * nn[t];
            }
        }
    }
    for (; e < end; e++) {
        int p = edge[e];
        if (live) {
            float nn = dis[p];
            uint2 u = h8[(size_t)p * 10 + c];
            float2 a = bf2f(u.x), d = bf2f(u.y);
            acc.x += a.x * nn; acc.y += a.y * nn; acc.z += d.x * nn; acc.w += d.y * nn;
        }
    }

    float4 z = acc;
    if (live) {
        float4 bv = reinterpret_cast<const float4*>(b)[c];
        z.x = acc.x * dg + bv.x; z.y = acc.y * dg + bv.y;
        z.z = acc.z * dg + bv.z; z.w = acc.w * dg + bv.w;
    }
    unsigned mask = 0xFFFFu << (threadIdx.x & 16);
    float m = live ? fmaxf(fmaxf(z.x, z.y), fmaxf(z.z, z.w)) : -INFINITY;
#pragma unroll
    for (int o = 8; o > 0; o >>= 1) m = fmaxf(m, __shfl_xor_sync(mask, m, o));
    float ss = live ? (__expf(z.x - m) + __expf(z.y - m) + __expf(z.z - m) + __expf(z.w - m)) : 0.f;
#pragma unroll
    for (int o = 8; o > 0; o >>= 1) ss += __shfl_xor_sync(mask, ss, o);
    float l = m + __logf(ss);
    if (live) {
        reinterpret_cast<float4*>(out)[(size_t)g * 10 + c] =
            make_float4(z.x - l, z.y - l, z.z - l, z.w - l);
    }
}

// ----------------------------------------------------------------
extern "C" void kernel_launch(void* const* d_in, const int* in_sizes, int n_in,
                              void* d_out, int out_size)
{
    const float* x  = (const float*)d_in[0];
    const int*   ei = (const int*)  d_in[1];
    const float* W1 = (const float*)d_in[2];
    const float* b1 = (const float*)d_in[3];
    const float* W2 = (const float*)d_in[4];
    const float* b2 = (const float*)d_in[5];
    float* out = (float*)d_out;

    const int n = in_sizes[0] / F_IN;
    const int E = in_sizes[1] / 2;
    const int* row = ei;
    const int* col = ei + E;

    float*    dis;   cudaGetSymbolAddress((void**)&dis,   g_dis);
    int*      cnt;   cudaGetSymbolAddress((void**)&cnt,   g_cnt);
    int*      ptr;   cudaGetSymbolAddress((void**)&ptr,   g_ptr);
    int*      rank;  cudaGetSymbolAddress((void**)&rank,  g_rank);
    int*      total; cudaGetSymbolAddress((void**)&total, g_total);
    int*      edge;  cudaGetSymbolAddress((void**)&edge,  g_edge);
    unsigned* h1;    cudaGetSymbolAddress((void**)&h1,    g_h1);
    unsigned* a1;    cudaGetSymbolAddress((void**)&a1,    g_a1);
    unsigned* h2;    cudaGetSymbolAddress((void**)&h2,    g_h2);

    const int B = 256;

    static cudaStream_t s2 = nullptr;
    static cudaEvent_t evF = nullptr, evJ = nullptr;
    static int init_done = 0;
    if (!init_done) {
        cudaFuncSetAttribute(k_gemm1, cudaFuncAttributeMaxDynamicSharedMemorySize, SMEM1_BYTES);
        cudaStreamCreateWithFlags(&s2, cudaStreamNonBlocking);
        cudaEventCreateWithFlags(&evF, cudaEventDisableTiming);
        cudaEventCreateWithFlags(&evJ, cudaEventDisableTiming);
        init_done = 1;
    }

    const int Ee = (E + 7) / 8;

    // fork: CSR build chain on s2, gemm1 on main stream (independent)
    cudaEventRecord(evF, 0);
    cudaStreamWaitEvent(s2, evF, 0);

    // submission order keeps gemm1 4th so the ncu window lands on it
    k_zero<<<(n + B - 1) / B, B, 0, s2>>>(cnt, total, n);
    k_hist<<<(Ee + B - 1) / B, B, 0, s2>>>(col, cnt, rank, E);
    k_ptr <<<(n + B - 1) / B, B, 0, s2>>>(cnt, ptr, dis, total, n);

    k_gemm1<<<(n + 255) / 256, 256, SMEM1_BYTES>>>(x, W1, h1, n);

    k_scat<<<(Ee + B - 1) / B, B, 0, s2>>>(row, col, ptr, rank, edge, E);
    cudaEventRecord(evJ, s2);

    // join: aggregation needs both gemm1 (main) and CSR (s2)
    cudaStreamWaitEvent(0, evJ, 0);

    k_agg1 <<<((n * 16) + B - 1) / B, B>>>(h1, edge, ptr, cnt, dis, b1, a1, n);
    k_gemm2<<<(n + 255) / 256, 128>>>(a1, W2, h2, n);
    k_agg2 <<<((n * 16) + B - 1) / B, B>>>(h2, edge, ptr, cnt, dis, b2, out, n);
}